// round 9
// baseline (speedup 1.0000x reference)
#include <cuda_runtime.h>

#define N_NODES   500000
#define E_EDGES   16000000
#define NVEC      (E_EDGES / 4)
#define NWARPS    (N_NODES / 32)         // 15625 warps, 32 nodes each
#define PAD       96                     // slots per node bucket (P(deg>96) ~ 1e-18)
#define SCAN_TILE 1024
#define NB_SCAN   ((N_NODES + SCAN_TILE - 1) / SCAN_TILE)   // 489

// ---------------------------------------------------------------------------
// Static scratch (allocation-free rule)
// ---------------------------------------------------------------------------
__device__ unsigned int  g_outcnt[N_NODES];
__device__ float         g_ds[N_NODES];              // out_deg^-0.5
__device__ float         g_dd[N_NODES];              // in_deg^-0.5
__device__ float         g_xs[N_NODES];              // y * ds
__device__ float         g_x2[N_NODES];              // layer-2 message
__device__ unsigned int  g_cursor[N_NODES];          // padded-bucket cursor (end after scatter)
__device__ unsigned int  g_off[N_NODES + 1];         // tight CSR offsets
__device__ unsigned int  g_blk[NB_SCAN];             // scan block sums
__device__ unsigned int  g_srcPad[N_NODES * PAD];    // padded buckets (build stage)
__device__ unsigned int  g_tight[E_EDGES];           // compact CSR adjacency (gather stage)

// ---------------------------------------------------------------------------
// 0. init cursors + zero out-degree
// ---------------------------------------------------------------------------
__global__ void init_cursor_kernel() {
    int i = blockIdx.x * blockDim.x + threadIdx.x;
    if (i < N_NODES) {
        g_cursor[i] = (unsigned int)i * PAD;
        g_outcnt[i] = 0u;
    }
}

// ---------------------------------------------------------------------------
// 1. fused scatter into padded buckets + out-degree REDs
// ---------------------------------------------------------------------------
__global__ void scatter_kernel(const int4* __restrict__ src4, const int4* __restrict__ dst4) {
    int i = blockIdx.x * blockDim.x + threadIdx.x;
    if (i >= NVEC) return;
    int4 s = __ldg(src4 + i);
    int4 d = __ldg(dst4 + i);
    atomicAdd(&g_outcnt[s.x], 1u);
    atomicAdd(&g_outcnt[s.y], 1u);
    atomicAdd(&g_outcnt[s.z], 1u);
    atomicAdd(&g_outcnt[s.w], 1u);
    unsigned int p0 = atomicAdd(&g_cursor[d.x], 1u);
    unsigned int p1 = atomicAdd(&g_cursor[d.y], 1u);
    unsigned int p2 = atomicAdd(&g_cursor[d.z], 1u);
    unsigned int p3 = atomicAdd(&g_cursor[d.w], 1u);
    g_srcPad[p0] = (unsigned int)s.x;
    g_srcPad[p1] = (unsigned int)s.y;
    g_srcPad[p2] = (unsigned int)s.z;
    g_srcPad[p3] = (unsigned int)s.w;
}

// ---------------------------------------------------------------------------
// 2a. scan stage 1: local exclusive scan of in-degrees (indeg = cursor - base)
// ---------------------------------------------------------------------------
__global__ __launch_bounds__(256) void scan1_kernel() {
    int tid  = threadIdx.x;
    int base = blockIdx.x * SCAN_TILE + tid * 4;
    unsigned int v[4], s = 0;
#pragma unroll
    for (int j = 0; j < 4; j++) {
        int idx = base + j;
        v[j] = (idx < N_NODES) ? (g_cursor[idx] - (unsigned int)idx * PAD) : 0u;
        s += v[j];
    }
    unsigned int x = s;
    int lane = tid & 31, warp = tid >> 5;
#pragma unroll
    for (int o = 1; o < 32; o <<= 1) {
        unsigned int y = __shfl_up_sync(0xffffffffu, x, o);
        if (lane >= o) x += y;
    }
    __shared__ unsigned int wsum[8];
    if (lane == 31) wsum[warp] = x;
    __syncthreads();
    if (warp == 0) {
        unsigned int w = (lane < 8) ? wsum[lane] : 0u;
#pragma unroll
        for (int o = 1; o < 8; o <<= 1) {
            unsigned int y = __shfl_up_sync(0xffffffffu, w, o);
            if (lane >= o) w += y;
        }
        if (lane < 8) wsum[lane] = w;
    }
    __syncthreads();
    unsigned int excl = x - s + (warp ? wsum[warp - 1] : 0u);
#pragma unroll
    for (int j = 0; j < 4; j++) {
        int idx = base + j;
        if (idx < N_NODES) g_off[idx] = excl;   // local exclusive; global add in stage 3
        excl += v[j];
    }
    if (tid == 255) g_blk[blockIdx.x] = excl;
}

// ---------------------------------------------------------------------------
// 2b. scan stage 2: exclusive scan of block sums
// ---------------------------------------------------------------------------
__global__ __launch_bounds__(512) void scan2_kernel() {
    __shared__ unsigned int bufA[512], bufB[512];
    int tid = threadIdx.x;
    unsigned int v = (tid < NB_SCAN) ? g_blk[tid] : 0u;
    bufA[tid] = v;
    __syncthreads();
    unsigned int *in = bufA, *out = bufB;
    for (int d = 1; d < 512; d <<= 1) {
        unsigned int x = in[tid];
        if (tid >= d) x += in[tid - d];
        out[tid] = x;
        __syncthreads();
        unsigned int* t = in; in = out; out = t;
    }
    if (tid < NB_SCAN) g_blk[tid] = in[tid] - v;
}

// ---------------------------------------------------------------------------
// 2c. scan stage 3 + node init: finalize tight offsets, degree norms,
//     y sign fix, first message
// ---------------------------------------------------------------------------
__global__ __launch_bounds__(256) void scan3_init_kernel(const float* __restrict__ y_in,
                                                         float* __restrict__ y) {
    int tid  = threadIdx.x;
    unsigned int add = g_blk[blockIdx.x];
    int base = blockIdx.x * SCAN_TILE + tid * 4;
#pragma unroll
    for (int j = 0; j < 4; j++) {
        int i = base + j;
        if (i >= N_NODES) break;
        g_off[i] += add;
        unsigned int indeg = g_cursor[i] - (unsigned int)i * PAD;
        float ds = rsqrtf(fmaxf((float)g_outcnt[i], 1.0f));
        float dd = rsqrtf(fmaxf((float)indeg, 1.0f));
        g_ds[i] = ds;
        g_dd[i] = dd;
        float yv = y_in[i];
        yv = (yv == 0.0f) ? -1.0f : yv;
        y[i]    = yv;
        g_xs[i] = yv * ds;
    }
    if (blockIdx.x == 0 && tid == 0) g_off[N_NODES] = E_EDGES;
}

// ---------------------------------------------------------------------------
// 3. repack: padded buckets -> compact CSR (warp per node)
// ---------------------------------------------------------------------------
__global__ __launch_bounds__(256) void repack_kernel() {
    int gt = blockIdx.x * blockDim.x + threadIdx.x;
    int n = gt >> 5;
    if (n >= N_NODES) return;
    int lane = gt & 31;
    unsigned int basep = (unsigned int)n * PAD;
    unsigned int deg   = g_cursor[n] - basep;
    unsigned int dst   = g_off[n];
    for (unsigned int i = lane; i < deg; i += 32)
        g_tight[dst + i] = g_srcPad[basep + i];
}

// ---------------------------------------------------------------------------
// Warp-cooperative aggregate, two nodes in flight (from R8, compact CSR).
// ---------------------------------------------------------------------------
__device__ __forceinline__ float warp_seg_gather2(const float* __restrict__ vals,
                                                  unsigned int my_lo, unsigned int my_hi,
                                                  int lane) {
    float myAgg = 0.0f;
#pragma unroll 1
    for (int k = 0; k < 16; k++) {
        unsigned int lo0 = __shfl_sync(0xffffffffu, my_lo, k);
        unsigned int hi0 = __shfl_sync(0xffffffffu, my_hi, k);
        unsigned int lo1 = __shfl_sync(0xffffffffu, my_lo, k + 16);
        unsigned int hi1 = __shfl_sync(0xffffffffu, my_hi, k + 16);
        float a0 = 0.0f, a1 = 0.0f;
        unsigned int i0 = lo0 + lane;
        unsigned int i1 = lo1 + lane;
        while (i0 < hi0 && i1 < hi1) {
            unsigned int s0 = __ldg(g_tight + i0);
            unsigned int s1 = __ldg(g_tight + i1);
            a0 += __ldg(vals + s0);
            a1 += __ldg(vals + s1);
            i0 += 32; i1 += 32;
        }
        while (i0 < hi0) { a0 += __ldg(vals + __ldg(g_tight + i0)); i0 += 32; }
        while (i1 < hi1) { a1 += __ldg(vals + __ldg(g_tight + i1)); i1 += 32; }
#pragma unroll
        for (int o = 16; o > 0; o >>= 1) {
            a0 += __shfl_xor_sync(0xffffffffu, a0, o);
            a1 += __shfl_xor_sync(0xffffffffu, a1, o);
        }
        if (lane == k)      myAgg = a0;
        if (lane == k + 16) myAgg = a1;
    }
    return myAgg;
}

// ---------------------------------------------------------------------------
// 4a. fused pass A: agg = A·xs ; fc+resid+LN+PReLU + layer-2 fc -> g_x2
// ---------------------------------------------------------------------------
__global__ __launch_bounds__(256) void passA_kernel(const float* __restrict__ y,
        const float* __restrict__ W1,  const float* __restrict__ b1,
        const float* __restrict__ Wres,
        const float* __restrict__ lng, const float* __restrict__ lnb,
        const float* __restrict__ pa,
        const float* __restrict__ W2,  const float* __restrict__ b2) {
    int gt = blockIdx.x * blockDim.x + threadIdx.x;
    int w  = gt >> 5;
    if (w >= NWARPS) return;
    int lane = gt & 31;
    int n = w * 32 + lane;

    unsigned int my_lo = __ldg(g_off + n);
    unsigned int my_hi = __ldg(g_off + n + 1);
    float a = warp_seg_gather2(g_xs, my_lo, my_hi, lane);

    float yv = __ldg(y + n);
    float ds = g_ds[n];
    float dd = g_dd[n];
    float alpha = __ldg(pa);
    float bias2 = __ldg(b2);

    float r[8]; float mu = 0.f;
#pragma unroll
    for (int j = 0; j < 8; j++) {
        r[j] = (a * __ldg(W1 + j) + __ldg(b1 + j)) * dd + yv * __ldg(Wres + j);
        mu += r[j];
    }
    mu *= 0.125f;
    float var = 0.f;
#pragma unroll
    for (int j = 0; j < 8; j++) { float u = r[j] - mu; var += u * u; }
    var *= 0.125f;
    float inv = rsqrtf(var + 1e-5f);
    float dot = 0.f;
#pragma unroll
    for (int j = 0; j < 8; j++) {
        float u = (r[j] - mu) * inv * __ldg(lng + j) + __ldg(lnb + j);
        u = (u >= 0.f) ? u : alpha * u;
        dot += u * __ldg(W2 + j);
    }
    g_x2[n] = ds * dot + bias2;
}

// ---------------------------------------------------------------------------
// 4b. fused pass B: agg2 = A·x2 ; y += dd*agg2 ; xs = y*ds
// ---------------------------------------------------------------------------
__global__ __launch_bounds__(256) void passB_kernel(float* __restrict__ y) {
    int gt = blockIdx.x * blockDim.x + threadIdx.x;
    int w  = gt >> 5;
    if (w >= NWARPS) return;
    int lane = gt & 31;
    int n = w * 32 + lane;

    unsigned int my_lo = __ldg(g_off + n);
    unsigned int my_hi = __ldg(g_off + n + 1);
    float a = warp_seg_gather2(g_x2, my_lo, my_hi, lane);

    float yv = y[n] + a * g_dd[n];
    y[n]    = yv;
    g_xs[n] = yv * g_ds[n];
}

// ---------------------------------------------------------------------------
// launch
// ---------------------------------------------------------------------------
extern "C" void kernel_launch(void* const* d_in, const int* in_sizes, int n_in,
                              void* d_out, int out_size) {
    const float* y_in = (const float*)d_in[0];
    const int*   src  = (const int*)d_in[1];
    const int*   dst  = (const int*)d_in[2];
    const float* W1   = (const float*)d_in[3];
    const float* b1   = (const float*)d_in[4];
    const float* Wres = (const float*)d_in[5];
    const float* lng  = (const float*)d_in[6];
    const float* lnb  = (const float*)d_in[7];
    const float* pa   = (const float*)d_in[8];
    const float* W2   = (const float*)d_in[9];
    const float* b2   = (const float*)d_in[10];
    float* y = (float*)d_out;

    const int TB = 256;
    int nb_n  = (N_NODES + TB - 1) / TB;
    int nb_e  = (NVEC + TB - 1) / TB;
    int nb_w  = (NWARPS * 32 + TB - 1) / TB;
    int nb_rp = (N_NODES * 32 + TB - 1) / TB;

    init_cursor_kernel<<<nb_n, TB>>>();
    scatter_kernel<<<nb_e, TB>>>((const int4*)src, (const int4*)dst);
    scan1_kernel<<<NB_SCAN, 256>>>();
    scan2_kernel<<<1, 512>>>();
    scan3_init_kernel<<<NB_SCAN, 256>>>(y_in, y);
    repack_kernel<<<nb_rp, TB>>>();

    for (int l = 0; l < 4; l++) {
        passA_kernel<<<nb_w, TB>>>(y, W1, b1, Wres, lng, lnb, pa, W2, b2);
        passB_kernel<<<nb_w, TB>>>(y);
    }
}

// round 10
// speedup vs baseline: 1.1582x; 1.1582x over previous
#include <cuda_runtime.h>

#define N_NODES   500000
#define E_EDGES   16000000
#define NVEC      (E_EDGES / 4)
#define NWARPS    (N_NODES / 32)         // 15625 warps, 32 nodes each
#define PAD       96                     // slots per node bucket (P(deg>96) ~ 1e-18)

// ---------------------------------------------------------------------------
// Static scratch (allocation-free rule)
// ---------------------------------------------------------------------------
__device__ unsigned int  g_outcnt[N_NODES];
__device__ float         g_ds[N_NODES];              // out_deg^-0.5
__device__ float         g_dd[N_NODES];              // in_deg^-0.5
__device__ float         g_xs[N_NODES];              // y * ds
__device__ float         g_x2[N_NODES];              // layer-2 message
__device__ unsigned int  g_end[N_NODES];             // bucket end (=cursor after scatter)
__device__ unsigned int  g_cursor[N_NODES];
__device__ unsigned int  g_srcSorted[N_NODES * PAD]; // padded buckets of src ids by dst

// ---------------------------------------------------------------------------
// 0. init cursors + zero out-degree
// ---------------------------------------------------------------------------
__global__ void init_cursor_kernel() {
    int i = blockIdx.x * blockDim.x + threadIdx.x;
    if (i < N_NODES) {
        g_cursor[i] = (unsigned int)i * PAD;
        g_outcnt[i] = 0u;
    }
}

// ---------------------------------------------------------------------------
// 1. fused scatter: place src ids into dst buckets + out-degree REDs
// ---------------------------------------------------------------------------
__global__ void scatter_kernel(const int4* __restrict__ src4, const int4* __restrict__ dst4) {
    int i = blockIdx.x * blockDim.x + threadIdx.x;
    if (i >= NVEC) return;
    int4 s = __ldg(src4 + i);
    int4 d = __ldg(dst4 + i);
    atomicAdd(&g_outcnt[s.x], 1u);
    atomicAdd(&g_outcnt[s.y], 1u);
    atomicAdd(&g_outcnt[s.z], 1u);
    atomicAdd(&g_outcnt[s.w], 1u);
    unsigned int p0 = atomicAdd(&g_cursor[d.x], 1u);
    unsigned int p1 = atomicAdd(&g_cursor[d.y], 1u);
    unsigned int p2 = atomicAdd(&g_cursor[d.z], 1u);
    unsigned int p3 = atomicAdd(&g_cursor[d.w], 1u);
    g_srcSorted[p0] = (unsigned int)s.x;
    g_srcSorted[p1] = (unsigned int)s.y;
    g_srcSorted[p2] = (unsigned int)s.z;
    g_srcSorted[p3] = (unsigned int)s.w;
}

// ---------------------------------------------------------------------------
// 2. node init: degree norms (in-degree from cursor), y sign fix, first msg
// ---------------------------------------------------------------------------
__global__ void init_kernel(const float* __restrict__ y_in, float* __restrict__ y) {
    int i = blockIdx.x * blockDim.x + threadIdx.x;
    if (i >= N_NODES) return;
    unsigned int end = g_cursor[i];
    g_end[i] = end;
    float indeg = (float)(end - (unsigned int)i * PAD);
    float ds = rsqrtf(fmaxf((float)g_outcnt[i], 1.0f));
    float dd = rsqrtf(fmaxf(indeg, 1.0f));
    g_ds[i] = ds;
    g_dd[i] = dd;
    float yv = y_in[i];
    yv = (yv == 0.0f) ? -1.0f : yv;
    y[i]    = yv;
    g_xs[i] = yv * ds;
}

// ---------------------------------------------------------------------------
// Sub-warp (8-lane) cooperative gather: warp covers 32 nodes in 8 rounds of
// 4 concurrent nodes. Per node: 3 shfl-xor reduce + 1 placement shfl.
// Returns this lane's node aggregate (node = warpNode0 + lane).
// ---------------------------------------------------------------------------
__device__ __forceinline__ float warp_gather_sw8(const float* __restrict__ vals,
                                                 int warpNode0, int lane) {
    int sw = lane >> 3;     // sub-warp id 0..3
    int sl = lane & 7;      // lane within sub-warp
    float myAgg = 0.0f;
#pragma unroll 2
    for (int r = 0; r < 8; r++) {
        int node = warpNode0 + r * 4 + sw;
        unsigned int lo = (unsigned int)node * PAD;
        unsigned int hi = __ldg(g_end + node);
        float a = 0.0f;
        for (unsigned int i = lo + sl; i < hi; i += 8)
            a += __ldg(vals + __ldg(g_srcSorted + i));
        // reduce within 8-lane group
        a += __shfl_xor_sync(0xffffffffu, a, 1);
        a += __shfl_xor_sync(0xffffffffu, a, 2);
        a += __shfl_xor_sync(0xffffffffu, a, 4);
        // place: lane L (= r*4 + sw') takes result computed by sub-warp sw'
        float got = __shfl_sync(0xffffffffu, a, (lane & 3) << 3);
        if ((lane >> 2) == r) myAgg = got;
    }
    return myAgg;
}

// ---------------------------------------------------------------------------
// 3a. fused pass A: agg = A·xs ; fc+resid+LN+PReLU + layer-2 fc -> g_x2
//     one warp per 32 nodes
// ---------------------------------------------------------------------------
__global__ __launch_bounds__(256) void passA_kernel(const float* __restrict__ y,
        const float* __restrict__ W1,  const float* __restrict__ b1,
        const float* __restrict__ Wres,
        const float* __restrict__ lng, const float* __restrict__ lnb,
        const float* __restrict__ pa,
        const float* __restrict__ W2,  const float* __restrict__ b2) {
    int gt = blockIdx.x * blockDim.x + threadIdx.x;
    int w  = gt >> 5;
    if (w >= NWARPS) return;
    int lane = gt & 31;
    int n = w * 32 + lane;

    float a = warp_gather_sw8(g_xs, w * 32, lane);

    float yv = __ldg(y + n);
    float ds = g_ds[n];
    float dd = g_dd[n];
    float alpha = __ldg(pa);
    float bias2 = __ldg(b2);

    float r[8]; float mu = 0.f;
#pragma unroll
    for (int j = 0; j < 8; j++) {
        r[j] = (a * __ldg(W1 + j) + __ldg(b1 + j)) * dd + yv * __ldg(Wres + j);
        mu += r[j];
    }
    mu *= 0.125f;
    float var = 0.f;
#pragma unroll
    for (int j = 0; j < 8; j++) { float u = r[j] - mu; var += u * u; }
    var *= 0.125f;
    float inv = rsqrtf(var + 1e-5f);
    float dot = 0.f;
#pragma unroll
    for (int j = 0; j < 8; j++) {
        float u = (r[j] - mu) * inv * __ldg(lng + j) + __ldg(lnb + j);
        u = (u >= 0.f) ? u : alpha * u;
        dot += u * __ldg(W2 + j);
    }
    g_x2[n] = ds * dot + bias2;
}

// ---------------------------------------------------------------------------
// 3b. fused pass B: agg2 = A·x2 ; y += dd*agg2 ; xs = y*ds
// ---------------------------------------------------------------------------
__global__ __launch_bounds__(256) void passB_kernel(float* __restrict__ y) {
    int gt = blockIdx.x * blockDim.x + threadIdx.x;
    int w  = gt >> 5;
    if (w >= NWARPS) return;
    int lane = gt & 31;
    int n = w * 32 + lane;

    float a = warp_gather_sw8(g_x2, w * 32, lane);

    float yv = y[n] + a * g_dd[n];
    y[n]    = yv;
    g_xs[n] = yv * g_ds[n];
}

// ---------------------------------------------------------------------------
// launch
// ---------------------------------------------------------------------------
extern "C" void kernel_launch(void* const* d_in, const int* in_sizes, int n_in,
                              void* d_out, int out_size) {
    const float* y_in = (const float*)d_in[0];
    const int*   src  = (const int*)d_in[1];
    const int*   dst  = (const int*)d_in[2];
    const float* W1   = (const float*)d_in[3];
    const float* b1   = (const float*)d_in[4];
    const float* Wres = (const float*)d_in[5];
    const float* lng  = (const float*)d_in[6];
    const float* lnb  = (const float*)d_in[7];
    const float* pa   = (const float*)d_in[8];
    const float* W2   = (const float*)d_in[9];
    const float* b2   = (const float*)d_in[10];
    float* y = (float*)d_out;

    const int TB = 256;
    int nb_n = (N_NODES + TB - 1) / TB;
    int nb_e = (NVEC + TB - 1) / TB;
    int nb_w = (NWARPS * 32 + TB - 1) / TB;

    init_cursor_kernel<<<nb_n, TB>>>();
    scatter_kernel<<<nb_e, TB>>>((const int4*)src, (const int4*)dst);
    init_kernel<<<nb_n, TB>>>(y_in, y);

    for (int l = 0; l < 4; l++) {
        passA_kernel<<<nb_w, TB>>>(y, W1, b1, Wres, lng, lnb, pa, W2, b2);
        passB_kernel<<<nb_w, TB>>>(y);
    }
}